// round 12
// baseline (speedup 1.0000x reference)
#include <cuda_runtime.h>
#include <cuda_fp16.h>

// Problem shape (fixed by the dataset):
//   A: [32, 4096, 64] f32, B: [32, 64, 4096] f32, index: [32, 4096, 32] i32
//   C[b,m,t] = sum_k A[b,m,k] * B[b,k,index[b,m,t]]
#define BB   32
#define MDIM 4096
#define KDIM 64
#define NDIM 4096
#define TOPK 32
#define NTILE 64
#define NSM   148
#define GRID_PERS (NSM * 6)              // 888 blocks, all co-resident
#define TOTAL_M  (BB * MDIM)             // 131072
#define CHUNK    886                     // ceil(TOTAL_M / NSM)

// 16 MB scratch: transposed B in fp16. Bt16[b][n][k] — one gathered row is
// 64 halves = 128 B = exactly one L1 line (1 wavefront per gather group).
__device__ __half2 g_Bt16[(size_t)BB * NDIM * (KDIM / 2)];

// ---------------------------------------------------------------------------
// Kernel 1: transpose+convert B[b,k,n] f32 -> Bt16[b,n,k] fp16.
// 64x64 tiles; each thread emits one 16B (8-half) chunk via STG.128.
// grid: (NDIM/64, BB), block: (32, 16)
// ---------------------------------------------------------------------------
__global__ void __launch_bounds__(512) transpose_kernel(const float* __restrict__ B) {
    __shared__ float tile[KDIM][NTILE + 1];   // 64 x 65 floats
    const int b  = blockIdx.y;
    const int n0 = blockIdx.x * NTILE;
    const int tx = threadIdx.x;        // 0..31
    const int ty = threadIdx.y;        // 0..15

    const float* Bb = B + (size_t)b * KDIM * NDIM;
    #pragma unroll
    for (int k = ty; k < KDIM; k += 16) {
        tile[k][tx]      = Bb[(size_t)k * NDIM + n0 + tx];        // coalesced
        tile[k][tx + 32] = Bb[(size_t)k * NDIM + n0 + tx + 32];
    }
    __syncthreads();

    const int tid = ty * 32 + tx;      // 0..511
    const int row = tid >> 3;          // 0..63  (n within tile)
    const int c   = tid & 7;           // 16B chunk: k = 8c..8c+7
    uint4 out;
    __half2* o2 = reinterpret_cast<__half2*>(&out);
    #pragma unroll
    for (int i = 0; i < 4; i++)
        o2[i] = __floats2half2_rn(tile[8 * c + 2 * i][row], tile[8 * c + 2 * i + 1][row]);

    // warp writes 4 consecutive 128B rows = 512B contiguous
    __half2* dst = g_Bt16 + (size_t)b * NDIM * 32 + (size_t)(n0 + row) * 32;
    reinterpret_cast<uint4*>(dst)[c] = out;
}

// ---------------------------------------------------------------------------
// Kernel 2: gather + dot. Warp-persistent, barrier-free, smem-free,
// BATCH-AFFINE: slot = bid % 148; the 6 blocks of a slot co-reside on one SM
// (wave-1 placement congruence) and share one contiguous 886-mi chunk, so
// each SM's gathers stay within ~one batch slice (512 KB hot set) -> L1 hits
// cut L2 traffic. A/idx use ld.cg and C uses st.cg to keep L1 for gathers.
// Lane layout: g = lane>>3 (4 groups), j = lane&7; iteration i computes
// t = 4i+g; deferred 3-round butterfly (XOR 1,2,4) transposes+reduces with
// the same summation tree as before -> bit-identical results.
// grid: 888, block: 256
// ---------------------------------------------------------------------------
__global__ void __launch_bounds__(256, 6) gather_dot_kernel(
    const float* __restrict__ A,
    const int*   __restrict__ index,
    float*       __restrict__ C)
{
    const int warp = threadIdx.x >> 5;
    const int lane = threadIdx.x & 31;
    const int j    = lane & 7;
    const int g    = lane >> 3;
    const int t_store = 4 * j + g;               // bijection on 0..31

    const int slot = blockIdx.x % NSM;           // SM-slot (co-resident group)
    const int wave = blockIdx.x / NSM;           // 0..5
    const int ws   = wave * 8 + warp;            // warp rank within slot, 0..47
    const int base = slot * CHUNK;

    for (int u = ws; u < CHUNK; u += 48) {
        const int mi = base + u;
        if (mi >= TOTAL_M) break;
        const int b = mi >> 12;                  // mi / MDIM
        const int m = mi & (MDIM - 1);

        const char* BtB = reinterpret_cast<const char*>(g_Bt16 + (size_t)b * NDIM * (KDIM / 2));

        // A row: lane j holds floats [8j, 8j+8), converted to half2 once.
        // ld.cg: streamed once, keep out of L1.
        const float4* A4 = reinterpret_cast<const float4*>(A + ((size_t)b * MDIM + m) * KDIM);
        const float4 a0 = __ldcg(&A4[2 * j]);
        const float4 a1 = __ldcg(&A4[2 * j + 1]);
        const __half2 ah0 = __floats2half2_rn(a0.x, a0.y);
        const __half2 ah1 = __floats2half2_rn(a0.z, a0.w);
        const __half2 ah2 = __floats2half2_rn(a1.x, a1.y);
        const __half2 ah3 = __floats2half2_rn(a1.z, a1.w);

        // lane t holds byte offset of row index[t] (pre-scaled)
        const int myoff = __ldcg(&index[((size_t)b * MDIM + m) * TOPK + lane]) * 128;

        float p[8];

        #pragma unroll
        for (int i = 0; i < 8; i++) {
            const int offv = __shfl_sync(0xffffffffu, myoff, 4 * i + g);
            // gathered row = 128 B; lane j reads its 16B slice (8 halves), ld.ca
            const uint4 bv = __ldg(reinterpret_cast<const uint4*>(BtB + offv) + j);

            __half2 acc =       __hmul2(ah0, *reinterpret_cast<const __half2*>(&bv.x));
            acc = __hfma2(ah1, *reinterpret_cast<const __half2*>(&bv.y), acc);
            acc = __hfma2(ah2, *reinterpret_cast<const __half2*>(&bv.z), acc);
            acc = __hfma2(ah3, *reinterpret_cast<const __half2*>(&bv.w), acc);

            const float2 f = __half22float2(acc);
            p[i] = f.x + f.y;
        }

        // Butterfly transpose-reduce over the 8-lane group (bit-identical tree).
        const int ja = j & 1, jb = (j >> 1) & 1, jc = (j >> 2) & 1;
        float q[4];
        #pragma unroll
        for (int d = 0; d < 4; d++) {
            const float give = ja ? p[2 * d] : p[2 * d + 1];
            const float keep = ja ? p[2 * d + 1] : p[2 * d];
            q[d] = keep + __shfl_xor_sync(0xffffffffu, give, 1);
        }   // q[d] ~ i = 2d + ja
        float r0, r1;
        {
            const float give0 = jb ? q[0] : q[1];
            const float keep0 = jb ? q[1] : q[0];
            r0 = keep0 + __shfl_xor_sync(0xffffffffu, give0, 2);   // i = 2jb + ja
            const float give1 = jb ? q[2] : q[3];
            const float keep1 = jb ? q[3] : q[2];
            r1 = keep1 + __shfl_xor_sync(0xffffffffu, give1, 2);   // i = 4 + 2jb + ja
        }
        const float give = jc ? r0 : r1;
        const float keep = jc ? r1 : r0;
        const float total = keep + __shfl_xor_sync(0xffffffffu, give, 4);
        // lane holds i = j  ->  t = 4j + g = t_store

        // one 128B line, permuted within line; st.cg keeps C out of L1
        __stcg(&C[((size_t)b * MDIM + m) * TOPK + t_store], total);
    }
}

// ---------------------------------------------------------------------------
extern "C" void kernel_launch(void* const* d_in, const int* in_sizes, int n_in,
                              void* d_out, int out_size) {
    const float* A   = (const float*)d_in[0];
    const float* B   = (const float*)d_in[1];
    const int*   idx = (const int*)d_in[2];
    float*       C   = (float*)d_out;

    transpose_kernel<<<dim3(NDIM / NTILE, BB), dim3(32, 16)>>>(B);
    gather_dot_kernel<<<GRID_PERS, 256>>>(A, idx, C);
}

// round 13
// speedup vs baseline: 1.0237x; 1.0237x over previous
#include <cuda_runtime.h>
#include <cuda_fp16.h>

// Problem shape (fixed by the dataset):
//   A: [32, 4096, 64] f32, B: [32, 64, 4096] f32, index: [32, 4096, 32] i32
//   C[b,m,t] = sum_k A[b,m,k] * B[b,k,index[b,m,t]]
#define BB   32
#define MDIM 4096
#define KDIM 64
#define NDIM 4096
#define TOPK 32
#define NTILE 64
#define NSM   148
#define GRID_PERS (NSM * 6)              // 888 blocks, all co-resident (wave 1)
#define TOTAL_M  (BB * MDIM)             // 131072
#define CHUNK    886                     // ceil(TOTAL_M / NSM)

// 16 MB scratch: transposed B in fp16. Bt16[b][n][k] — one gathered row is
// 64 halves = 128 B = exactly one L1 line (1 wavefront per gather group).
__device__ __half2 g_Bt16[(size_t)BB * NDIM * (KDIM / 2)];

// ---------------------------------------------------------------------------
// Kernel 1: transpose+convert B[b,k,n] f32 -> Bt16[b,n,k] fp16.
// 64x64 tiles; each thread emits one 16B (8-half) chunk via STG.128.
// grid: (NDIM/64, BB), block: (32, 16)
// ---------------------------------------------------------------------------
__global__ void __launch_bounds__(512) transpose_kernel(const float* __restrict__ B) {
    __shared__ float tile[KDIM][NTILE + 1];   // 64 x 65 floats
    const int b  = blockIdx.y;
    const int n0 = blockIdx.x * NTILE;
    const int tx = threadIdx.x;        // 0..31
    const int ty = threadIdx.y;        // 0..15

    const float* Bb = B + (size_t)b * KDIM * NDIM;
    #pragma unroll
    for (int k = ty; k < KDIM; k += 16) {
        tile[k][tx]      = Bb[(size_t)k * NDIM + n0 + tx];        // coalesced
        tile[k][tx + 32] = Bb[(size_t)k * NDIM + n0 + tx + 32];
    }
    __syncthreads();

    const int tid = ty * 32 + tx;      // 0..511
    const int row = tid >> 3;          // 0..63  (n within tile)
    const int c   = tid & 7;           // 16B chunk: k = 8c..8c+7
    uint4 out;
    __half2* o2 = reinterpret_cast<__half2*>(&out);
    #pragma unroll
    for (int i = 0; i < 4; i++)
        o2[i] = __floats2half2_rn(tile[8 * c + 2 * i][row], tile[8 * c + 2 * i + 1][row]);

    // warp writes 4 consecutive 128B rows = 512B contiguous
    __half2* dst = g_Bt16 + (size_t)b * NDIM * 32 + (size_t)(n0 + row) * 32;
    reinterpret_cast<uint4*>(dst)[c] = out;
}

// ---------------------------------------------------------------------------
// Kernel 2: gather + dot. Warp-persistent, barrier-free, smem-free.
// CLUSTER-2 launch: placement becomes contiguous-modular (smid=(bid+142)%148),
// so the 6 blocks with bid ≡ slot (mod 148) genuinely co-reside on one SM and
// share one contiguous 886-m chunk (~one batch slice, 512 KB hot rows) ->
// repeated gathers hit in L1 and cut the L2 traffic that R11 was capped on.
// No cluster sync is used — the attribute is for placement only.
// Lane layout: g = lane>>3 (4 groups), j = lane&7 (8 lanes read one gathered
// 128B fp16 row: 1 LDG.128 each); iteration i computes t = 4i+g; deferred
// 3-round butterfly (XOR 1,2,4) transposes+reduces with the same summation
// tree as R8..R12 -> bit-identical results.
// grid: 888, block: 256
// ---------------------------------------------------------------------------
__global__ void __launch_bounds__(256, 6) __cluster_dims__(2, 1, 1)
gather_dot_kernel(
    const float* __restrict__ A,
    const int*   __restrict__ index,
    float*       __restrict__ C)
{
    const int warp = threadIdx.x >> 5;
    const int lane = threadIdx.x & 31;
    const int j    = lane & 7;
    const int g    = lane >> 3;
    const int t_store = 4 * j + g;               // bijection on 0..31

    const int slot = blockIdx.x % NSM;           // co-resident group (CLC mod placement)
    const int wave = blockIdx.x / NSM;           // 0..5
    const int ws   = wave * 8 + warp;            // warp rank within slot, 0..47
    const int base = slot * CHUNK;

    for (int u = ws; u < CHUNK; u += 48) {
        const int mi = base + u;
        if (mi >= TOTAL_M) break;
        const int b = mi >> 12;                  // mi / MDIM
        const int m = mi & (MDIM - 1);

        const char* BtB = reinterpret_cast<const char*>(g_Bt16 + (size_t)b * NDIM * (KDIM / 2));

        // A row: lane j holds floats [8j, 8j+8), converted to half2 once
        const float4* A4 = reinterpret_cast<const float4*>(A + ((size_t)b * MDIM + m) * KDIM);
        const float4 a0 = __ldg(&A4[2 * j]);
        const float4 a1 = __ldg(&A4[2 * j + 1]);
        const __half2 ah0 = __floats2half2_rn(a0.x, a0.y);
        const __half2 ah1 = __floats2half2_rn(a0.z, a0.w);
        const __half2 ah2 = __floats2half2_rn(a1.x, a1.y);
        const __half2 ah3 = __floats2half2_rn(a1.z, a1.w);

        // lane t holds byte offset of row index[t] (pre-scaled)
        const int myoff = __ldg(&index[((size_t)b * MDIM + m) * TOPK + lane]) * 128;

        float p[8];

        #pragma unroll
        for (int i = 0; i < 8; i++) {
            const int offv = __shfl_sync(0xffffffffu, myoff, 4 * i + g);
            // gathered row = 128 B; lane j reads its 16B slice (8 halves)
            const uint4 bv = __ldg(reinterpret_cast<const uint4*>(BtB + offv) + j);

            __half2 acc =       __hmul2(ah0, *reinterpret_cast<const __half2*>(&bv.x));
            acc = __hfma2(ah1, *reinterpret_cast<const __half2*>(&bv.y), acc);
            acc = __hfma2(ah2, *reinterpret_cast<const __half2*>(&bv.z), acc);
            acc = __hfma2(ah3, *reinterpret_cast<const __half2*>(&bv.w), acc);

            const float2 f = __half22float2(acc);
            p[i] = f.x + f.y;
        }

        // Butterfly transpose-reduce over the 8-lane group (bit-identical tree).
        const int ja = j & 1, jb = (j >> 1) & 1, jc = (j >> 2) & 1;
        float q[4];
        #pragma unroll
        for (int d = 0; d < 4; d++) {
            const float give = ja ? p[2 * d] : p[2 * d + 1];
            const float keep = ja ? p[2 * d + 1] : p[2 * d];
            q[d] = keep + __shfl_xor_sync(0xffffffffu, give, 1);
        }   // q[d] ~ i = 2d + ja
        float r0, r1;
        {
            const float give0 = jb ? q[0] : q[1];
            const float keep0 = jb ? q[1] : q[0];
            r0 = keep0 + __shfl_xor_sync(0xffffffffu, give0, 2);   // i = 2jb + ja
            const float give1 = jb ? q[2] : q[3];
            const float keep1 = jb ? q[3] : q[2];
            r1 = keep1 + __shfl_xor_sync(0xffffffffu, give1, 2);   // i = 4 + 2jb + ja
        }
        const float give = jc ? r0 : r1;
        const float keep = jc ? r1 : r0;
        const float total = keep + __shfl_xor_sync(0xffffffffu, give, 4);
        // lane holds i = j  ->  t = 4j + g = t_store

        // one 128B line, permuted within line: 1 store wavefront per m
        C[((size_t)b * MDIM + m) * TOPK + t_store] = total;
    }
}

// ---------------------------------------------------------------------------
extern "C" void kernel_launch(void* const* d_in, const int* in_sizes, int n_in,
                              void* d_out, int out_size) {
    const float* A   = (const float*)d_in[0];
    const float* B   = (const float*)d_in[1];
    const int*   idx = (const int*)d_in[2];
    float*       C   = (float*)d_out;

    transpose_kernel<<<dim3(NDIM / NTILE, BB), dim3(32, 16)>>>(B);
    gather_dot_kernel<<<GRID_PERS, 256>>>(A, idx, C);
}